// round 17
// baseline (speedup 1.0000x reference)
#include <cuda_runtime.h>
#include <cuda_fp16.h>
#include <math.h>
#include <stdint.h>

#define SEQ      4096
#define DMODEL   256
#define DINNER   512
#define DSTATE   64
#define NHEADS   8
#define HEADDIM  64
#define CONVDIM  640
#define DPROJ    1160
#define MTOT     32768          // 8 * 4096 rows (concat of both batch stacks)
#define NSEG     32
#define SEGLEN   128            // SEQ / NSEG
#define NSCANBLK 2048           // 8b * 8h * 32seg (full head per block)
#define DT_TILE  9              // in-proj N tile containing the dt columns

// ---------------- scratch (static device globals; no allocations allowed) ----
__device__ __half g_zxh  [(size_t)MTOT * DPROJ];
__device__ __half g_xconv[(size_t)MTOT * CONVDIM];
__device__ float  g_yraw [(size_t)MTOT * DINNER];
__device__ float  g_sp   [(size_t)MTOT * DMODEL];
__device__ float  g_u    [(size_t)MTOT * DMODEL];
__device__ float  g_cda  [(size_t)MTOT * NHEADS];
__device__ float  g_hseg [(size_t)NSCANBLK * 4096];
__device__ float  g_h0s  [(size_t)NSCANBLK * 4096];

// fp16 activations
__device__ __half g_xnh[(size_t)MTOT * DMODEL];
__device__ __half g_ynh[(size_t)MTOT * DINNER];
__device__ __half g_sph[(size_t)MTOT * DMODEL];
__device__ __half g_hmh[(size_t)MTOT * DMODEL];

// fp16 weights (in-proj keeps hi/lo split for the dt tile; others hi only)
__device__ __half g_Winh[DPROJ * DMODEL], g_Winl[DPROJ * DMODEL];
__device__ __half g_Wouth[DMODEL * DINNER];
__device__ __half g_w1h[DMODEL * DINNER];
__device__ __half g_w2h[DMODEL * DMODEL];

__device__ __forceinline__ float siluf(float x) {
    return x / (1.f + expf(-x));
}
__device__ __forceinline__ float2 h2f(uint32_t u) {
    __half2 h = *(__half2*)&u;
    return __half22float2(h);
}
__device__ __forceinline__ uint32_t smem_u32(const void* p) {
    uint32_t a;
    asm("{ .reg .u64 t; cvta.to.shared.u64 t, %1; cvt.u32.u64 %0, t; }" : "=r"(a) : "l"(p));
    return a;
}
#define LDSM4(d0, d1, d2, d3, a) \
    asm volatile("ldmatrix.sync.aligned.m8n8.x4.shared.b16 {%0,%1,%2,%3}, [%4];" \
                 : "=r"(d0), "=r"(d1), "=r"(d2), "=r"(d3) : "r"(a))
__device__ __forceinline__ void mma_fp16(float* d, const uint32_t* a, const uint32_t* b) {
    asm volatile(
        "mma.sync.aligned.m16n8k16.row.col.f32.f16.f16.f32 "
        "{%0,%1,%2,%3}, {%4,%5,%6,%7}, {%8,%9}, {%0,%1,%2,%3};"
        : "+f"(d[0]), "+f"(d[1]), "+f"(d[2]), "+f"(d[3])
        : "r"(a[0]), "r"(a[1]), "r"(a[2]), "r"(a[3]), "r"(b[0]), "r"(b[1]));
}

// ------ fused: LayerNorm(concat) -> fp16 (warp per row) + weight tail -------
#define PRE_LN_BLKS (MTOT / 8)       // 4096
#define PRE_W_BLKS  145              // 145 * 2048 = 296960 = DPROJ*DMODEL
__global__ void __launch_bounds__(256) pre_kernel(
    const float* __restrict__ x0, const float* __restrict__ x1,
    const float* __restrict__ w,  const float* __restrict__ bias,
    const float* __restrict__ W_in, const float* __restrict__ W_out,
    const float* __restrict__ w1,  const float* __restrict__ w2)
{
    int blk = blockIdx.x;
    int tid = threadIdx.x;
    if (blk >= PRE_LN_BLKS) {
        int i0 = (blk - PRE_LN_BLKS) * 2048 + tid * 8;
        #pragma unroll
        for (int j = 0; j < 8; j += 4) {
            int i = i0 + j;
            float4 v = *(const float4*)(W_in + i);
            __half h0 = __float2half(v.x), h1 = __float2half(v.y);
            __half h2 = __float2half(v.z), h3 = __float2half(v.w);
            __half2 hh0; hh0.x = h0; hh0.y = h1;
            __half2 hh1; hh1.x = h2; hh1.y = h3;
            *(uint2*)(g_Winh + i) = make_uint2(*(uint32_t*)&hh0, *(uint32_t*)&hh1);
            __half2 ll0 = __floats2half2_rn(v.x - __half2float(h0), v.y - __half2float(h1));
            __half2 ll1 = __floats2half2_rn(v.z - __half2float(h2), v.w - __half2float(h3));
            *(uint2*)(g_Winl + i) = make_uint2(*(uint32_t*)&ll0, *(uint32_t*)&ll1);
            if (i < DMODEL * DINNER) {
                float4 a = *(const float4*)(W_out + i);
                float4 c = *(const float4*)(w1 + i);
                __half2 a01 = __floats2half2_rn(a.x, a.y), a23 = __floats2half2_rn(a.z, a.w);
                __half2 c01 = __floats2half2_rn(c.x, c.y), c23 = __floats2half2_rn(c.z, c.w);
                *(uint2*)(g_Wouth + i) = make_uint2(*(uint32_t*)&a01, *(uint32_t*)&a23);
                *(uint2*)(g_w1h + i)   = make_uint2(*(uint32_t*)&c01, *(uint32_t*)&c23);
            }
            if (i < DMODEL * DMODEL) {
                float4 c = *(const float4*)(w2 + i);
                __half2 c01 = __floats2half2_rn(c.x, c.y), c23 = __floats2half2_rn(c.z, c.w);
                *(uint2*)(g_w2h + i) = make_uint2(*(uint32_t*)&c01, *(uint32_t*)&c23);
            }
        }
        return;
    }
    int wd = tid >> 5, lid = tid & 31;
    int m = blk * 8 + wd;
    int b = m >> 12;
    int t = m & 4095;
    const float* src = (b < 4) ? (x0 + ((size_t)(b * SEQ + t)) * DMODEL)
                               : (x1 + ((size_t)((b - 4) * SEQ + t)) * DMODEL);
    int c0 = lid * 8;
    float4 v0 = *(const float4*)(src + c0);
    float4 v1 = *(const float4*)(src + c0 + 4);
    float s  = (v0.x + v0.y + v0.z + v0.w) + (v1.x + v1.y + v1.z + v1.w);
    float s2 = (v0.x*v0.x + v0.y*v0.y + v0.z*v0.z + v0.w*v0.w)
             + (v1.x*v1.x + v1.y*v1.y + v1.z*v1.z + v1.w*v1.w);
    #pragma unroll
    for (int o = 16; o; o >>= 1) {
        s  += __shfl_xor_sync(0xffffffffu, s,  o);
        s2 += __shfl_xor_sync(0xffffffffu, s2, o);
    }
    float mu  = s  * (1.f / 256.f);
    float var = s2 * (1.f / 256.f) - mu * mu;
    float r = rsqrtf(var + 1e-5f);
    float4 w0 = *(const float4*)(w + c0);
    float4 w1v = *(const float4*)(w + c0 + 4);
    float4 b0 = *(const float4*)(bias + c0);
    float4 b1 = *(const float4*)(bias + c0 + 4);
    __half2 o0 = __floats2half2_rn((v0.x - mu) * r * w0.x + b0.x, (v0.y - mu) * r * w0.y + b0.y);
    __half2 o1 = __floats2half2_rn((v0.z - mu) * r * w0.z + b0.z, (v0.w - mu) * r * w0.w + b0.w);
    __half2 o2 = __floats2half2_rn((v1.x - mu) * r * w1v.x + b1.x, (v1.y - mu) * r * w1v.y + b1.y);
    __half2 o3 = __floats2half2_rn((v1.z - mu) * r * w1v.z + b1.z, (v1.w - mu) * r * w1v.w + b1.w);
    *(uint4*)(g_xnh + (size_t)m * DMODEL + c0) =
        make_uint4(*(uint32_t*)&o0, *(uint32_t*)&o1, *(uint32_t*)&o2, *(uint32_t*)&o3);
}

// ---------------- final LayerNorm (warp per row): g_u -> d_out ---------------
__global__ void __launch_bounds__(256) ln_t_kernel(
    const float* __restrict__ w, const float* __restrict__ bias,
    float* __restrict__ out)
{
    int wd = threadIdx.x >> 5, lid = threadIdx.x & 31;
    int m = blockIdx.x * 8 + wd;
    int c0 = lid * 8;
    const float* src = g_u + (size_t)m * DMODEL;
    float4 v0 = *(const float4*)(src + c0);
    float4 v1 = *(const float4*)(src + c0 + 4);
    float s  = (v0.x + v0.y + v0.z + v0.w) + (v1.x + v1.y + v1.z + v1.w);
    float s2 = (v0.x*v0.x + v0.y*v0.y + v0.z*v0.z + v0.w*v0.w)
             + (v1.x*v1.x + v1.y*v1.y + v1.z*v1.z + v1.w*v1.w);
    #pragma unroll
    for (int o = 16; o; o >>= 1) {
        s  += __shfl_xor_sync(0xffffffffu, s,  o);
        s2 += __shfl_xor_sync(0xffffffffu, s2, o);
    }
    float mu  = s  * (1.f / 256.f);
    float var = s2 * (1.f / 256.f) - mu * mu;
    float r = rsqrtf(var + 1e-5f);
    float4 w0 = *(const float4*)(w + c0);
    float4 w1v = *(const float4*)(w + c0 + 4);
    float4 b0 = *(const float4*)(bias + c0);
    float4 b1 = *(const float4*)(bias + c0 + 4);
    float* dst = out + (size_t)m * DMODEL + c0;
    *(float4*)dst = make_float4((v0.x - mu) * r * w0.x + b0.x, (v0.y - mu) * r * w0.y + b0.y,
                                (v0.z - mu) * r * w0.z + b0.z, (v0.w - mu) * r * w0.w + b0.w);
    *(float4*)(dst + 4) = make_float4((v1.x - mu) * r * w1v.x + b1.x, (v1.y - mu) * r * w1v.y + b1.y,
                                      (v1.z - mu) * r * w1v.z + b1.z, (v1.w - mu) * r * w1v.w + b1.w);
}

// ---------------- depthwise conv (k=4) + SiLU -> fp16, 4 timesteps/thread ---
__global__ void conv_kernel(const float* __restrict__ conv_w, const float* __restrict__ conv_b)
{
    int idx = blockIdx.x * blockDim.x + threadIdx.x;
    if (idx >= (MTOT / 4) * CONVDIM) return;
    int c  = idx % CONVDIM;
    int m4 = idx / CONVDIM;
    int b  = m4 >> 10;
    int t0 = (m4 & 1023) << 2;
    const __half* base = g_zxh + (size_t)(b * SEQ) * DPROJ + DINNER + c;
    float4 w4 = *(const float4*)(conv_w + c * 4);
    float bia = conv_b[c];
    float v[7];
    #pragma unroll
    for (int j = 0; j < 7; j++) {
        int tt = t0 - 3 + j;
        v[j] = (tt >= 0) ? __half2float(base[(size_t)tt * DPROJ]) : 0.f;
    }
    size_t obase = (size_t)(b * SEQ + t0) * CONVDIM + c;
    #pragma unroll
    for (int i = 0; i < 4; i++) {
        float acc = bia;
        acc = fmaf(v[i + 0], w4.x, acc);
        acc = fmaf(v[i + 1], w4.y, acc);
        acc = fmaf(v[i + 2], w4.z, acc);
        acc = fmaf(v[i + 3], w4.w, acc);
        g_xconv[obase + (size_t)i * CONVDIM] = __float2half(siluf(acc));
    }
}

// ========== Pass A: chunked-SSD local scan (tensor cores), h0=0 per segment ==
#define OFF_SB   0
#define OFF_SC   9216
#define OFF_SXT  18432
#define OFF_SGA  35840
#define OFF_SBV  53248
#define OFF_SDT  62464
#define OFF_SS   62720
#define OFF_SCDA 62976
#define OFF_SVH  63232
#define SA_BYTES 63360
__global__ void __launch_bounds__(256, 2) scan_seg_kernel(
    const float* __restrict__ dt_bias, const float* __restrict__ A_log,
    const float* __restrict__ D_param)
{
    extern __shared__ char smraw[];
    __half* sB  = (__half*)(smraw + OFF_SB);
    __half* sC  = (__half*)(smraw + OFF_SC);
    __half* sXT = (__half*)(smraw + OFF_SXT);
    __half* sGa = (__half*)(smraw + OFF_SGA);
    __half* sBv = (__half*)(smraw + OFF_SBV);
    float*  sdt = (float*)(smraw + OFF_SDT);
    float*  sS  = (float*)(smraw + OFF_SS);
    float*  scda= (float*)(smraw + OFF_SCDA);
    __half* svh = (__half*)(smraw + OFF_SVH);

    int blk = blockIdx.x;
    int seg = blk & 31;
    int h   = (blk >> 5) & 7;
    int b   = blk >> 8;
    int tid = threadIdx.x;
    int wid = tid >> 5, lane = tid & 31;
    int wm  = wid >> 1, wn = wid & 1;   // 4 x 2 warp grid over 64x64
    int gq  = lane >> 2, tq = lane & 3;
    int q   = lane >> 3, r5 = lane & 7;

    float hfrag[4][4];
    #pragma unroll
    for (int ni = 0; ni < 4; ni++)
        #pragma unroll
        for (int r = 0; r < 4; r++) hfrag[ni][r] = 0.f;
    float prevcum = 1.f;

    float Dh  = D_param[h];
    float eA  = expf(A_log[h]);
    float dtb = dt_bias[h];
    const __half* xbase = g_xconv + (size_t)b * SEQ * CONVDIM;
    int pofs = h * 64;

    #pragma unroll 1
    for (int cc = 0; cc < 2; cc++) {
        int c0 = seg * SEGLEN + cc * 64;

        // --- A: stage x rows (temp in sGa), B, C; compute dt ---
        #pragma unroll
        for (int i = 0; i < 2; i++) {
            int idx = i * 256 + tid;
            int t = idx >> 3, n8 = (idx & 7) * 8;
            const __half* rowp = xbase + (size_t)(c0 + t) * CONVDIM;
            *(uint4*)(sGa + t * 136 + n8) = *(const uint4*)(rowp + pofs + n8);
            *(uint4*)(sB  + t * 72  + n8) = *(const uint4*)(rowp + 512 + n8);
            *(uint4*)(sC  + t * 72  + n8) = *(const uint4*)(rowp + 576 + n8);
        }
        if (tid < 64) {
            float raw = __half2float(g_zxh[(size_t)(b * SEQ + c0 + tid) * DPROJ + (DPROJ - NHEADS) + h]) + dtb;
            sdt[tid] = (raw > 20.f) ? raw : log1pf(expf(raw));
        }
        __syncthreads();

        // --- B: prefix sum S (warp 0); cda/v; transpose x; stage h0 ---
        if (wid == 0) {
            float d0 = sdt[2 * lane], d1 = sdt[2 * lane + 1];
            float acc = d0 + d1;
            #pragma unroll
            for (int o = 1; o < 32; o <<= 1) {
                float vv = __shfl_up_sync(0xffffffffu, acc, o);
                if (lane >= o) acc += vv;
            }
            sS[2 * lane]     = acc - d1;
            sS[2 * lane + 1] = acc;
        }
        __syncthreads();
        if (tid < 64) {
            float cda = __expf(-eA * sS[tid]);
            scda[tid] = cda;
            g_cda[(size_t)(b * SEQ + c0 + tid) * NHEADS + h] = prevcum * cda;
            float Send = sS[63];
            svh[tid] = __float2half(__expf(eA * (sS[tid] - Send)) * sdt[tid]);
        }
        #pragma unroll
        for (int i = 0; i < 16; i++) {
            int idx = i * 256 + tid;
            int p = idx >> 6, t = idx & 63;
            sXT[p * 136 + t] = sGa[t * 136 + p];
        }
        if (cc == 0) {
            #pragma unroll
            for (int i = 0; i < 2; i++) {
                int idx = i * 256 + tid;
                int p = idx >> 3, n8 = (idx & 7) * 8;
                *(uint4*)(sXT + p * 136 + 64 + n8) = make_uint4(0, 0, 0, 0);
            }
        } else {
            #pragma unroll
            for (int ni = 0; ni < 4; ni++) {
                int n = wn * 32 + ni * 8 + 2 * tq;
                int p0 = wm * 16 + gq, p1 = p0 + 8;
                *(__half2*)(sXT + p0 * 136 + 64 + n) = __floats2half2_rn(hfrag[ni][0], hfrag[ni][1]);
                *(__half2*)(sXT + p1 * 136 + 64 + n) = __floats2half2_rn(hfrag[ni][2], hfrag[ni][3]);
            }
        }
        __syncthreads();

        // --- C: GEMM1 G = C @ B^T ---
        float gacc[4][4];
        #pragma unroll
        for (int ni = 0; ni < 4; ni++)
            #pragma unroll
            for (int r = 0; r < 4; r++) gacc[ni][r] = 0.f;
        #pragma unroll
        for (int kc = 0; kc < 64; kc += 16) {
            uint32_t a[4];
            {
                int arow = wm * 16 + (q & 1) * 8 + r5;
                int acol = kc + (q >> 1) * 8;
                LDSM4(a[0], a[1], a[2], a[3], smem_u32(sC + arow * 72 + acol));
            }
            uint32_t bf[4][2];
            #pragma unroll
            for (int nb = 0; nb < 2; nb++) {
                int brow = wn * 32 + nb * 16 + (q >> 1) * 8 + r5;
                int bcol = kc + (q & 1) * 8;
                LDSM4(bf[2 * nb][0], bf[2 * nb][1], bf[2 * nb + 1][0], bf[2 * nb + 1][1],
                      smem_u32(sB + brow * 72 + bcol));
            }
            #pragma unroll
            for (int ni = 0; ni < 4; ni++) mma_fp16(gacc[ni], a, bf[ni]);
        }

        // --- D: mask G -> sGa[.,0:64]; aug cda*C -> sGa[.,64:128]; Bv ---
        #pragma unroll
        for (int ni = 0; ni < 4; ni++) {
            int s0 = wn * 32 + ni * 8 + 2 * tq;
            int t0 = wm * 16 + gq, t1 = t0 + 8;
            float St0 = sS[t0], St1 = sS[t1];
            float Ss0 = sS[s0], Ss1 = sS[s0 + 1];
            float d0 = sdt[s0], d1 = sdt[s0 + 1];
            float w00 = (s0     <= t0) ? __expf(eA * (Ss0 - St0)) * d0 : 0.f;
            float w01 = (s0 + 1 <= t0) ? __expf(eA * (Ss1 - St0)) * d1 : 0.f;
            float w10 = (s0     <= t1) ? __expf(eA * (Ss0 - St1)) * d0 : 0.f;
            float w11 = (s0 + 1 <= t1) ? __expf(eA * (Ss1 - St1)) * d1 : 0.f;
            *(__half2*)(sGa + t0 * 136 + s0) = __floats2half2_rn(gacc[ni][0] * w00, gacc[ni][1] * w01);
            *(__half2*)(sGa + t1 * 136 + s0) = __floats2half2_rn(gacc[ni][2] * w10, gacc[ni][3] * w11);
        }
        #pragma unroll
        for (int i = 0; i < 2; i++) {
            int idx = i * 256 + tid;
            int t = idx >> 3, n8 = (idx & 7) * 8;
            uint4 cu = *(uint4*)(sC + t * 72 + n8);
            __half2 sc = __float2half2_rn(scda[t]);
            __half2* cp = (__half2*)&cu;
            cp[0] = __hmul2(cp[0], sc); cp[1] = __hmul2(cp[1], sc);
            cp[2] = __hmul2(cp[2], sc); cp[3] = __hmul2(cp[3], sc);
            *(uint4*)(sGa + t * 136 + 64 + n8) = cu;
        }
        #pragma unroll
        for (int i = 0; i < 16; i++) {
            int idx = i * 256 + tid;
            int n = idx >> 6, s = idx & 63;
            sBv[n * 72 + s] = __hmul(sB[s * 72 + n], svh[s]);
        }
        __syncthreads();

        // --- E: GEMM2 Y = Ga @ [X;h0] + epilogue ---
        float yacc[4][4];
        #pragma unroll
        for (int ni = 0; ni < 4; ni++)
            #pragma unroll
            for (int r = 0; r < 4; r++) yacc[ni][r] = 0.f;
        #pragma unroll
        for (int kc = 0; kc < 128; kc += 16) {
            uint32_t a[4];
            {
                int arow = wm * 16 + (q & 1) * 8 + r5;
                int acol = kc + (q >> 1) * 8;
                LDSM4(a[0], a[1], a[2], a[3], smem_u32(sGa + arow * 136 + acol));
            }
            uint32_t bf[4][2];
            #pragma unroll
            for (int nb = 0; nb < 2; nb++) {
                int brow = wn * 32 + nb * 16 + (q >> 1) * 8 + r5;
                int bcol = kc + (q & 1) * 8;
                LDSM4(bf[2 * nb][0], bf[2 * nb][1], bf[2 * nb + 1][0], bf[2 * nb + 1][1],
                      smem_u32(sXT + brow * 136 + bcol));
            }
            #pragma unroll
            for (int ni = 0; ni < 4; ni++) mma_fp16(yacc[ni], a, bf[ni]);
        }
        #pragma unroll
        for (int ni = 0; ni < 4; ni++) {
            int p0 = wn * 32 + ni * 8 + 2 * tq;
            int t0 = wm * 16 + gq, t1 = t0 + 8;
            float x00 = __half2float(sXT[p0 * 136 + t0]);
            float x01 = __half2float(sXT[(p0 + 1) * 136 + t0]);
            float x10 = __half2float(sXT[p0 * 136 + t1]);
            float x11 = __half2float(sXT[(p0 + 1) * 136 + t1]);
            float* y0 = g_yraw + (size_t)(b * SEQ + c0 + t0) * DINNER + pofs;
            float* y1 = g_yraw + (size_t)(b * SEQ + c0 + t1) * DINNER + pofs;
            *(float2*)(y0 + p0) = make_float2(fmaf(Dh, x00, yacc[ni][0]), fmaf(Dh, x01, yacc[ni][1]));
            *(float2*)(y1 + p0) = make_float2(fmaf(Dh, x10, yacc[ni][2]), fmaf(Dh, x11, yacc[ni][3]));
        }

        // --- F: h update ---
        float cend = scda[63];
        #pragma unroll
        for (int ni = 0; ni < 4; ni++)
            #pragma unroll
            for (int r = 0; r < 4; r++) hfrag[ni][r] *= cend;
        #pragma unroll
        for (int kc = 0; kc < 64; kc += 16) {
            uint32_t a[4];
            {
                int arow = wm * 16 + (q & 1) * 8 + r5;
                int acol = kc + (q >> 1) * 8;
                LDSM4(a[0], a[1], a[2], a[3], smem_u32(sXT + arow * 136 + acol));
            }
            uint32_t bf[4][2];
            #pragma unroll
            for (int nb = 0; nb < 2; nb++) {
                int brow = wn * 32 + nb * 16 + (q >> 1) * 8 + r5;
                int bcol = kc + (q & 1) * 8;
                LDSM4(bf[2 * nb][0], bf[2 * nb][1], bf[2 * nb + 1][0], bf[2 * nb + 1][1],
                      smem_u32(sBv + brow * 72 + bcol));
            }
            #pragma unroll
            for (int ni = 0; ni < 4; ni++) mma_fp16(hfrag[ni], a, bf[ni]);
        }
        prevcum *= cend;
        __syncthreads();
    }

    // export local end state h[p][n]
    #pragma unroll
    for (int ni = 0; ni < 4; ni++) {
        int n = wn * 32 + ni * 8 + 2 * tq;
        int p0 = wm * 16 + gq, p1 = p0 + 8;
        *(float2*)(g_hseg + (size_t)blk * 4096 + p0 * 64 + n) = make_float2(hfrag[ni][0], hfrag[ni][1]);
        *(float2*)(g_hseg + (size_t)blk * 4096 + p1 * 64 + n) = make_float2(hfrag[ni][2], hfrag[ni][3]);
    }
}

// ========== Pass B: sequential combine across segments =======================
__global__ void __launch_bounds__(256) combine_kernel()
{
    int blk = blockIdx.x;
    int tid = threadIdx.x;
    int h = blk & 7;
    int b = blk >> 3;
    float hstart[16];
    #pragma unroll
    for (int j = 0; j < 16; j++) hstart[j] = 0.f;
    for (int s = 0; s < NSEG; s++) {
        size_t base = ((size_t)(blk * NSEG + s)) * 4096 + tid * 16;
        #pragma unroll
        for (int j = 0; j < 4; j++)
            *(float4*)(g_h0s + base + j * 4) =
                make_float4(hstart[j*4], hstart[j*4+1], hstart[j*4+2], hstart[j*4+3]);
        float P = g_cda[(size_t)(b * SEQ + s * SEGLEN + SEGLEN - 1) * NHEADS + h];
        #pragma unroll
        for (int j = 0; j < 4; j++) {
            float4 v = *(const float4*)(g_hseg + base + j * 4);
            hstart[j*4]   = fmaf(P, hstart[j*4],   v.x);
            hstart[j*4+1] = fmaf(P, hstart[j*4+1], v.y);
            hstart[j*4+2] = fmaf(P, hstart[j*4+2], v.z);
            hstart[j*4+3] = fmaf(P, hstart[j*4+3], v.w);
        }
    }
}

// ========== Pass C (tensor-core): y += cumdA_t * (C @ h0^T)[t,p] =============
#define SCROW 72
#define SC_BYTES (128 * SCROW * 2 + 64 * SCROW * 2 + 128 * 4)   // 28160
__global__ void __launch_bounds__(256) correct_kernel()
{
    int blk = blockIdx.x;
    int seg = blk & 31;
    if (seg == 0) return;
    extern __shared__ char smraw[];
    __half* sCt = (__half*)smraw;                      // [128][72]
    __half* sH  = (__half*)(smraw + 128 * SCROW * 2);  // [64][72]
    float*  scd = (float*)(smraw + 128 * SCROW * 2 + 64 * SCROW * 2);  // [128]

    int h   = (blk >> 5) & 7;
    int b   = blk >> 8;
    int tid = threadIdx.x;
    int wid = tid >> 5, lane = tid & 31;
    int wt  = wid >> 1, wp = wid & 1;
    int gq  = lane >> 2, tq = lane & 3;

    {
        const __half* Cb = g_xconv + ((size_t)(b * SEQ + seg * SEGLEN)) * CONVDIM + 576;
        #pragma unroll
        for (int i = 0; i < 4; i++) {
            int idx = i * 256 + tid;
            int t = idx >> 3, n8 = (idx & 7) * 8;
            *(uint4*)(sCt + t * SCROW + n8) = *(const uint4*)(Cb + (size_t)t * CONVDIM + n8);
        }
    }
    {
        const float* hb = g_h0s + (size_t)blk * 4096;
        #pragma unroll
        for (int i = 0; i < 4; i++) {
            int idx = i * 256 + tid;
            int p = idx >> 4, n4 = (idx & 15) * 4;
            float4 hv = *(const float4*)(hb + p * 64 + n4);
            __half2 h01 = __floats2half2_rn(hv.x, hv.y);
            __half2 h23 = __floats2half2_rn(hv.z, hv.w);
            *(uint2*)(sH + p * SCROW + n4) = make_uint2(*(uint32_t*)&h01, *(uint32_t*)&h23);
        }
    }
    if (tid < SEGLEN)
        scd[tid] = g_cda[(size_t)(b * SEQ + seg * SEGLEN + tid) * NHEADS + h];
    __syncthreads();

    float acc[2][4][4];
    #pragma unroll
    for (int mi = 0; mi < 2; mi++)
        #pragma unroll
        for (int ni = 0; ni < 4; ni++)
            #pragma unroll
            for (int r = 0; r < 4; r++) acc[mi][ni][r] = 0.f;

    uint32_t sc_base = smem_u32(sCt);
    uint32_t sh_base = smem_u32(sH);
    int q = lane >> 3, r = lane & 7;
    #pragma unroll
    for (int kc = 0; kc < 64; kc += 16) {
        uint32_t a[2][4];
        #pragma unroll
        for (int mi = 0; mi < 2; mi++) {
            int arow = wt * 32 + mi * 16 + (q & 1) * 8 + r;
            int acol = kc + (q >> 1) * 8;
            LDSM4(a[mi][0], a[mi][1], a[mi][2], a[mi][3],
                  sc_base + (arow * SCROW + acol) * 2);
        }
        uint32_t bf[4][2];
        #pragma unroll
        for (int nb = 0; nb < 2; nb++) {
            int brow = wp * 32 + nb * 16 + (q >> 1) * 8 + r;
            int bcol = kc + (q & 1) * 8;
            LDSM4(bf[2 * nb][0], bf[2 * nb][1], bf[2 * nb + 1][0], bf[2 * nb + 1][1],
                  sh_base + (brow * SCROW + bcol) * 2);
        }
        #pragma unroll
        for (int mi = 0; mi < 2; mi++)
            #pragma unroll
            for (int ni = 0; ni < 4; ni++)
                mma_fp16(acc[mi][ni], a[mi], bf[ni]);
    }

    int pofs = h * 64;
    #pragma unroll
    for (int mi = 0; mi < 2; mi++) {
        int t0 = wt * 32 + mi * 16 + gq;
        int t1 = t0 + 8;
        float s0 = scd[t0], s1 = scd[t1];
        float* y0 = g_yraw + (size_t)(b * SEQ + seg * SEGLEN + t0) * DINNER + pofs;
        float* y1 = g_yraw + (size_t)(b * SEQ + seg * SEGLEN + t1) * DINNER + pofs;
        #pragma unroll
        for (int ni = 0; ni < 4; ni++) {
            int p = wp * 32 + ni * 8 + 2 * tq;
            y0[p]     += s0 * acc[mi][ni][0];
            y0[p + 1] += s0 * acc[mi][ni][1];
            y1[p]     += s1 * acc[mi][ni][2];
            y1[p + 1] += s1 * acc[mi][ni][3];
        }
    }
}

// ---------------- gate with silu(z) + RMSNorm -> fp16 (warp per row) ---------
__global__ void __launch_bounds__(256) gate_rms_kernel(const float* __restrict__ rms_w)
{
    int wd = threadIdx.x >> 5, lid = threadIdx.x & 31;
    int m = blockIdx.x * 8 + wd;
    int c0 = lid * 16;
    const __half* zp = g_zxh + (size_t)m * DPROJ + c0;
    const float* yp = g_yraw + (size_t)m * DINNER + c0;
    uint4 zu0 = *(const uint4*)(zp);
    uint4 zu1 = *(const uint4*)(zp + 8);
    float zf[16];
    {
        float2 a;
        a = h2f(zu0.x); zf[0] = a.x;  zf[1] = a.y;
        a = h2f(zu0.y); zf[2] = a.x;  zf[3] = a.y;
        a = h2f(zu0.z); zf[4] = a.x;  zf[5] = a.y;
        a = h2f(zu0.w); zf[6] = a.x;  zf[7] = a.y;
        a = h2f(zu1.x); zf[8] = a.x;  zf[9] = a.y;
        a = h2f(zu1.y); zf[10] = a.x; zf[11] = a.y;
        a = h2f(zu1.z); zf[12] = a.x; zf[13] = a.y;
        a = h2f(zu1.w); zf[14] = a.x; zf[15] = a.y;
    }
    float g[16];
    float s2 = 0.f;
    #pragma unroll
    for (int j = 0; j < 16; j += 4) {
        float4 y = *(const float4*)(yp + j);
        g[j]     = y.x * siluf(zf[j]);
        g[j + 1] = y.y * siluf(zf[j + 1]);
        g[j + 2] = y.z * siluf(zf[j + 2]);
        g[j + 3] = y.w * siluf(zf[j + 3]);
        s2 += g[j]*g[j] + g[j+1]*g[j+1] + g[j+2]*g[j+2] + g[j+3]*g[j+3];
    }
    #pragma unroll
    for (int o = 16; o; o >>= 1) s2 += __shfl_xor_sync(0xffffffffu, s2, o);
    float r = rsqrtf(s2 * (1.f / 512.f) + 1e-5f);
    __half out8[16];
    #pragma unroll
    for (int j = 0; j < 16; j += 4) {
        float4 w4 = *(const float4*)(rms_w + c0 + j);
        out8[j]     = __float2half(g[j]     * r * w4.x);
        out8[j + 1] = __float2half(g[j + 1] * r * w4.y);
        out8[j + 2] = __float2half(g[j + 2] * r * w4.z);
        out8[j + 3] = __float2half(g[j + 3] * r * w4.w);
    }
    *(uint4*)(g_ynh + (size_t)m * DINNER + c0)     = *(uint4*)(out8);
    *(uint4*)(g_ynh + (size_t)m * DINNER + c0 + 8) = *(uint4*)(out8 + 8);
}

// ======== pipelined fp16 mma.sync GEMM ======================================
// MODE 0: in-proj -> fp16 g_zxh; 2nd product (Winl) ONLY on tile DT_TILE
// MODE 1: += x_cat residual; fp32 g_sp + fp16 g_sph   (out-proj)
// MODE 2: A gathered from g_sph; silu(+bias) -> fp16 g_hmh (mlp1)
// MODE 3: + bias + g_sp residual -> fp32 C                 (mlp2)
#define CP16(dst, src, sz) \
    asm volatile("cp.async.cg.shared.global [%0], [%1], 16, %2;" \
                 :: "r"(dst), "l"(src), "r"(sz))
#define CP_COMMIT() asm volatile("cp.async.commit_group;" ::: "memory")
template <int N>
__device__ __forceinline__ void cp_wait() {
    asm volatile("cp.async.wait_group %0;" :: "n"(N) : "memory");
}

#define ROWB     80
#define MATB     (128 * ROWB)        // 10240

template <int MODE, int NPROD, int NST>
__global__ void __launch_bounds__(256, 2) gemm_mma(
    const __half* __restrict__ Ah,
    const __half* __restrict__ Bh, const __half* __restrict__ Bl,
    float* __restrict__ C, int N, int K,
    const float* __restrict__ e0, const float* __restrict__ e1)
{
    constexpr int STAGEB = ((MODE == 0) ? 3 : (1 + NPROD)) * MATB;
    const bool use2 = (MODE == 0) ? (blockIdx.x == DT_TILE) : (NPROD == 2);
    extern __shared__ char smem[];
    uint32_t sb = smem_u32(smem);
    int tid  = threadIdx.x;
    int wid  = tid >> 5, lane = tid & 31;
    int wm   = wid >> 2, wn = wid & 3;
    int bm   = blockIdx.y * 128;
    int bn   = blockIdx.x * 128;
    int gq   = lane >> 2;
    int tq   = lane & 3;

    float acc[4][4][4];
    #pragma unroll
    for (int mi = 0; mi < 4; mi++)
        #pragma unroll
        for (int ni = 0; ni < 4; ni++)
            #pragma unroll
            for (int r = 0; r < 4; r++) acc[mi][ni][r] = 0.f;

    auto fill_stage = [&](int s, int k0) {
        uint32_t st = sb + s * STAGEB;
        #pragma unroll
        for (int j = 0; j < 2; j++) {
            int idx = j * 256 + tid;
            int row = idx >> 2, seg = idx & 3;
            const __half* sh;
            if (MODE == 2) {
                int gr = bm + row;
                int vv = gr >> 14;
                int base = gr & 16383;
                int kk = k0 + seg * 8;
                int usef1 = ((kk >= 256) ? 1 : 0) ^ vv;
                sh = g_sph + ((size_t)(base + (usef1 ? 16384 : 0))) * DMODEL + (kk & 255);
            } else {
                sh = Ah + (size_t)(bm + row) * K + k0 + seg * 8;
            }
            CP16(st + row * ROWB + seg * 16, sh, 16);
        }
        #pragma unroll
        for (int j = 0; j < 2; j++) {
            int idx = j * 256 + tid;
            int row = idx >> 2, seg = idx & 3;
            int gn = bn + row;
            int sz = (gn < N) ? 16 : 0;
            size_t off = (size_t)gn * K + k0 + seg * 8;
            uint32_t d = st + MATB + row * ROWB + seg * 16;
            CP16(d, Bh + off, sz);
            if (use2) CP16(d + MATB, Bl + off, sz);
        }
    };

    auto compute_stage = [&](int s) {
        uint32_t stA = sb + s * STAGEB;
        uint32_t stB = stA + MATB;
        int q = lane >> 3, r = lane & 7;
        #pragma unroll
        for (int ks = 0; ks < 2; ks++) {
            int kc = ks * 16;
            uint32_t ah[4][4];
            #pragma unroll
            for (int mi = 0; mi < 4; mi++) {
                int arow = wm * 64 + mi * 16 + (q & 1) * 8 + r;
                int acol = kc + (q >> 1) * 8;
                LDSM4(ah[mi][0], ah[mi][1], ah[mi][2], ah[mi][3],
                      stA + arow * ROWB + acol * 2);
            }
            uint32_t bh[4][2], bl[4][2];
            #pragma unroll
            for (int nb = 0; nb < 2; nb++) {
                int brow = wn * 32 + nb * 16 + (q >> 1) * 8 + r;
                int bcol = kc + (q & 1) * 8;
                uint32_t bd = stB + brow * ROWB + bcol * 2;
                LDSM4(bh[2 * nb][0], bh[2 * nb][1], bh[2 * nb + 1][0], bh[2 * nb + 1][1], bd);
                if (use2)
                    LDSM4(bl[2 * nb][0], bl[2 * nb][1], bl[2 * nb + 1][0], bl[2 * nb + 1][1], bd + MATB);
            }
            #pragma unroll
            for (int mi = 0; mi < 4; mi++)
                #pragma unroll
                for (int ni = 0; ni < 4; ni++) {
                    mma_fp16(acc[mi][ni], ah[mi], bh[ni]);
                    if (use2) mma_fp16(acc[mi][ni], ah[mi], bl[ni]);
                }
        }
    };

    int nk = K >> 5;
    #pragma unroll
    for (int s = 0; s < NST - 1; s++) {
        if (s < nk) { fill_stage(s, s << 5); }
        CP_COMMIT();
    }
    for (int i = 0; i < nk; i++) {
        cp_wait<NST - 2>();
        __syncthreads();
        if (i + NST - 1 < nk) fill_stage((i + NST - 1) % NST, (i + NST - 1) << 5);
        CP_COMMIT();
        compute_stage(i % NST);
    }

    // epilogue
    #pragma unroll
    for (int mi = 0; mi < 4; mi++) {
        int gr0 = bm + wm * 64 + mi * 16 + gq;
        int gr1 = gr0 + 8;
        const float *res0 = nullptr, *res1 = nullptr;
        if (MODE == 1) {
            int b0i = gr0 >> 12, t0 = gr0 & 4095;
            int b1i = gr1 >> 12, t1 = gr1 & 4095;
            res0 = (b0i < 4) ? (e0 + ((size_t)(b0i * SEQ + t0)) * DMODEL)
                             : (e1 + ((size_t)((b0i - 4) * SEQ + t0)) * DMODEL);
            res1 = (b1i < 4) ? (e0 + ((size_t)(b1i * SEQ + t1)) * DMODEL)
                             : (e1 + ((size_t)((b1i - 4) * SEQ + t1)) * DMODEL);
        }
        #pragma unroll
        for (int ni = 0; ni < 4; ni++) {
            int gc = bn + wn * 32 + ni * 8 + 2 * tq;
            if (gc >= N) continue;
            float v0 = acc[mi][ni][0], v1 = acc[mi][ni][1];
            float v2 = acc[mi][ni][2], v3 = acc[mi][ni][3];
            if (MODE == 0) {
                *(__half2*)(g_zxh + (size_t)gr0 * DPROJ + gc) = __floats2half2_rn(v0, v1);
                *(__half2*)(g_zxh + (size_t)gr1 * DPROJ + gc) = __floats2half2_rn(v2, v3);
            }
            if (MODE == 1) {
                v0 += res0[gc]; v1 += res0[gc + 1];
                v2 += res1[gc]; v3 += res1[gc + 1];
                *(float2*)(C + (size_t)gr0 * N + gc) = make_float2(v0, v1);
                *(float2*)(C + (size_t)gr1 * N + gc) = make_float2(v2, v3);
                *(__half2*)(g_sph + (size_t)gr0 * DMODEL + gc) = __floats2half2_rn(v0, v1);
                *(__half2*)(g_sph + (size_t)gr1 * DMODEL + gc) = __floats2half2_rn(v2, v3);
            }
            if (MODE == 2) {
                float bx = e0[gc], by = e0[gc + 1];
                v0 = siluf(v0 + bx); v1 = siluf(v1 + by);
                v2 = siluf(v2 + bx); v3 = siluf(v3 + by);
                *(__half2*)(g_hmh + (size_t)gr0 * DMODEL + gc) = __floats2half2_rn(v0, v1);
                *(__half2*)(g_hmh + (size_t)gr1 * DMODEL + gc) = __floats2half2_rn(v2, v3);
            }
            if (MODE == 3) {
                float bx = e0[gc], by = e0[gc + 1];
                const float* s0 = g_sp + (size_t)gr0 * DMODEL + gc;
                const float* s1 = g_sp + (size_t)gr1 * DMODEL + gc;
                v0 += bx + s0[0]; v1 += by + s0[1];
                v2 += bx + s1[0]; v3 += by + s1[1];
                *(float2*)(C + (size_t)gr0 * N + gc) = make_float2(v0, v1);
                *(float2*)(C + (size_t)gr1 * N + gc) = make_float2(v2, v3);
            }
        }
    }
}

// ---------------- launch ------------------------------------------------------
extern "C" void kernel_launch(void* const* d_in, const int* in_sizes, int n_in,
                              void* d_out, int out_size)
{
    const float* x0      = (const float*)d_in[0];
    const float* x1      = (const float*)d_in[1];
    const float* nsw     = (const float*)d_in[2];
    const float* nsb     = (const float*)d_in[3];
    const float* W_in    = (const float*)d_in[4];
    const float* conv_w  = (const float*)d_in[5];
    const float* conv_b  = (const float*)d_in[6];
    const float* dt_bias = (const float*)d_in[7];
    const float* A_log   = (const float*)d_in[8];
    const float* Dp      = (const float*)d_in[9];
    const float* rms_w   = (const float*)d_in[10];
    const float* W_out   = (const float*)d_in[11];
    const float* w1      = (const float*)d_in[12];
    const float* b1      = (const float*)d_in[13];
    const float* w2      = (const float*)d_in[14];
    const float* b2      = (const float*)d_in[15];
    const float* ntw     = (const float*)d_in[16];
    const float* ntb     = (const float*)d_in[17];
    float* out = (float*)d_out;

    float *p_sp, *p_u;
    cudaGetSymbolAddress((void**)&p_sp, g_sp);
    cudaGetSymbolAddress((void**)&p_u,  g_u);
    __half *p_xnh, *p_ynh, *p_hmh;
    __half *p_Winh, *p_Winl, *p_Wouth, *p_w1h, *p_w2h;
    cudaGetSymbolAddress((void**)&p_xnh, g_xnh);
    cudaGetSymbolAddress((void**)&p_ynh, g_ynh);
    cudaGetSymbolAddress((void**)&p_hmh, g_hmh);
    cudaGetSymbolAddress((void**)&p_Winh,  g_Winh);
    cudaGetSymbolAddress((void**)&p_Winl,  g_Winl);
    cudaGetSymbolAddress((void**)&p_Wouth, g_Wouth);
    cudaGetSymbolAddress((void**)&p_w1h,   g_w1h);
    cudaGetSymbolAddress((void**)&p_w2h,   g_w2h);

    const int SM0  = 2 * 3 * MATB;   // 61440 (MODE 0, NST=2, 3 mats)
    const int SM13 = 3 * 2 * MATB;   // 61440 (NPROD=1, NST=3)
    cudaFuncSetAttribute((const void*)gemm_mma<0, 1, 2>, cudaFuncAttributeMaxDynamicSharedMemorySize, SM0);
    cudaFuncSetAttribute((const void*)gemm_mma<1, 1, 3>, cudaFuncAttributeMaxDynamicSharedMemorySize, SM13);
    cudaFuncSetAttribute((const void*)gemm_mma<2, 1, 3>, cudaFuncAttributeMaxDynamicSharedMemorySize, SM13);
    cudaFuncSetAttribute((const void*)gemm_mma<3, 1, 3>, cudaFuncAttributeMaxDynamicSharedMemorySize, SM13);
    cudaFuncSetAttribute((const void*)scan_seg_kernel, cudaFuncAttributeMaxDynamicSharedMemorySize, SA_BYTES);
    cudaFuncSetAttribute((const void*)correct_kernel,  cudaFuncAttributeMaxDynamicSharedMemorySize, SC_BYTES);

    // #1: fused LayerNorm (warp/row) + weight convert
    pre_kernel<<<PRE_LN_BLKS + PRE_W_BLKS, 256>>>(x0, x1, nsw, nsb, W_in, W_out, w1, w2);

    // #2: in-proj GEMM (1-product except dt tile, fp16 out): zxbcdt = xn @ W_in^T
    gemm_mma<0, 1, 2><<<dim3((DPROJ + 127) / 128, MTOT / 128), 256, SM0>>>(
        p_xnh, p_Winh, p_Winl, nullptr, DPROJ, DMODEL, nullptr, nullptr);

    // #3: depthwise conv + SiLU -> fp16
    conv_kernel<<<((MTOT / 4) * CONVDIM + 255) / 256, 256>>>(conv_w, conv_b);

    // #4: pass A — chunked-SSD segmented scans, 2 CTAs/SM  [ncu captures this]
    scan_seg_kernel<<<NSCANBLK, 256, SA_BYTES>>>(dt_bias, A_log, Dp);

    // #5: pass B — combine segment states
    combine_kernel<<<64, 256>>>();

    // #6: pass C — cross-segment correction via tensor cores
    correct_kernel<<<NSCANBLK, 256, SC_BYTES>>>();

    // #7: gate + RMSNorm (warp/row) -> fp16
    gate_rms_kernel<<<MTOT / 8, 256>>>(rms_w);

    // #8: out-proj GEMM (1-product) + residual -> g_sp/g_sph
    gemm_mma<1, 1, 3><<<dim3(2, MTOT / 128), 256, SM13>>>(
        p_ynh, p_Wouth, nullptr, p_sp, DMODEL, DINNER, x0, x1);

    // #9: MLP layer 1 (1-product, cross-concat gather) + SiLU -> g_hmh
    gemm_mma<2, 1, 3><<<dim3(2, MTOT / 128), 256, SM13>>>(
        nullptr, p_w1h, nullptr, nullptr, DMODEL, DINNER, b1, nullptr);

    // #10: MLP layer 2 (1-product) + bias + g_sp residual -> g_u
    gemm_mma<3, 1, 3><<<dim3(2, MTOT / 128), 256, SM13>>>(
        p_hmh, p_w2h, nullptr, p_u, DMODEL, DMODEL, b2, nullptr);

    // #11: final LayerNorm (warp/row) -> d_out
    ln_t_kernel<<<MTOT / 8, 256>>>(ntw, ntb, out);

    (void)in_sizes; (void)n_in; (void)out_size;
}